// round 1
// baseline (speedup 1.0000x reference)
#include <cuda_runtime.h>
#include <math.h>

// ---------------------------------------------------------------------------
// EmformerEncoder  B=2, T=1248 (224 right-ctx + 1024 body), D=1024, H=16,
// DK=64, F=4096, L=2.  Mask is analytic (derived from CHUNK=128, LEFT=128,
// RIGHT=32): block-sparse attention, <=288 keys/query.
// Round 0: full-fp32 pipeline (precision-safe), classic 128x128x8 SGEMM.
// ---------------------------------------------------------------------------

#define TTOT   1248
#define NRIGHT 224
#define BATCH  2
#define MROWS  (BATCH * TTOT)   // 2496
#define DMODEL 1024
#define NHEAD  16
#define DK     64
#define FDIM   4096
#define NCHUNK 8

// ---- scratch (device globals; no allocation allowed) ----------------------
__device__ float g_h[MROWS * DMODEL];     // LN_in output (reused for LN1 out)
__device__ float g_q[MROWS * DMODEL];
__device__ float g_k[MROWS * DMODEL];
__device__ float g_v[MROWS * DMODEL];
__device__ float g_attn[MROWS * DMODEL];  // o + h  (residual hub)
__device__ float g_y1[MROWS * FDIM];
__device__ float g_y2[MROWS * DMODEL];
__device__ float g_x[MROWS * DMODEL];     // layer-0 output

// ---------------------------------------------------------------------------
// LayerNorm: one block per row, 256 threads, float4 per thread (256*4 = 1024)
// ---------------------------------------------------------------------------
__global__ void ln_kernel(const float* __restrict__ X,
                          const float* __restrict__ sc,
                          const float* __restrict__ bi,
                          float* __restrict__ Y)
{
    int row = blockIdx.x;
    int t   = threadIdx.x;
    const float4* xr = (const float4*)(X + (size_t)row * DMODEL);
    float4 v = xr[t];
    float s  = v.x + v.y + v.z + v.w;
    float ss = v.x*v.x + v.y*v.y + v.z*v.z + v.w*v.w;
    #pragma unroll
    for (int off = 16; off; off >>= 1) {
        s  += __shfl_xor_sync(0xffffffffu, s,  off);
        ss += __shfl_xor_sync(0xffffffffu, ss, off);
    }
    __shared__ float redS[8], redQ[8];
    int w = t >> 5;
    if ((t & 31) == 0) { redS[w] = s; redQ[w] = ss; }
    __syncthreads();
    float S = 0.f, Q = 0.f;
    #pragma unroll
    for (int i = 0; i < 8; i++) { S += redS[i]; Q += redQ[i]; }
    float mean = S * (1.0f / DMODEL);
    float var  = Q * (1.0f / DMODEL) - mean * mean;
    float r    = rsqrtf(var + 1e-5f);
    float4 scv = ((const float4*)sc)[t];
    float4 bv  = ((const float4*)bi)[t];
    float4 o;
    o.x = (v.x - mean) * r * scv.x + bv.x;
    o.y = (v.y - mean) * r * scv.y + bv.y;
    o.z = (v.z - mean) * r * scv.z + bv.z;
    o.w = (v.w - mean) * r * scv.w + bv.w;
    ((float4*)(Y + (size_t)row * DMODEL))[t] = o;
}

// ---------------------------------------------------------------------------
// SGEMM: C[M,N] = A[M,K] @ B[K,N] + bias[N] (+ res[M,N]).
// 128x128 block tile, 8x8 per thread, K-step 8, 256 threads.
// N, K multiples of 128/8; only M needs guarding (M = 2496).
// ---------------------------------------------------------------------------
__global__ void sgemm_kernel(const float* __restrict__ A,
                             const float* __restrict__ B,
                             const float* __restrict__ bias,
                             const float* __restrict__ res,
                             float* __restrict__ C,
                             int M, int N, int K)
{
    __shared__ __align__(16) float As[8][128];
    __shared__ __align__(16) float Bs[8][128];

    int bm = blockIdx.y * 128;
    int bn = blockIdx.x * 128;
    int tid = threadIdx.x;

    int arow = tid >> 1;            // 0..127
    int acol = (tid & 1) * 4;       // 0 or 4
    int brow = tid >> 5;            // 0..7
    int bcol = (tid & 31) * 4;      // 0..124

    int ty = (tid >> 4) * 8;        // row offset of 8x8 micro-tile
    int tx = (tid & 15) * 8;        // col offset

    float acc[8][8];
    #pragma unroll
    for (int i = 0; i < 8; i++)
        #pragma unroll
        for (int j = 0; j < 8; j++) acc[i][j] = 0.f;

    bool aValid = (bm + arow) < M;
    const float* Aptr = A + (size_t)(bm + arow) * K + acol;

    for (int k0 = 0; k0 < K; k0 += 8) {
        float4 av = make_float4(0.f, 0.f, 0.f, 0.f);
        if (aValid) av = *(const float4*)(Aptr + k0);
        As[acol + 0][arow] = av.x;
        As[acol + 1][arow] = av.y;
        As[acol + 2][arow] = av.z;
        As[acol + 3][arow] = av.w;
        float4 bv = *(const float4*)&B[(size_t)(k0 + brow) * N + bn + bcol];
        *(float4*)&Bs[brow][bcol] = bv;
        __syncthreads();

        #pragma unroll
        for (int kk = 0; kk < 8; kk++) {
            float a[8], b[8];
            *(float4*)(a)     = *(const float4*)&As[kk][ty];
            *(float4*)(a + 4) = *(const float4*)&As[kk][ty + 4];
            *(float4*)(b)     = *(const float4*)&Bs[kk][tx];
            *(float4*)(b + 4) = *(const float4*)&Bs[kk][tx + 4];
            #pragma unroll
            for (int i = 0; i < 8; i++)
                #pragma unroll
                for (int j = 0; j < 8; j++)
                    acc[i][j] += a[i] * b[j];
        }
        __syncthreads();
    }

    #pragma unroll
    for (int i = 0; i < 8; i++) {
        int row = bm + ty + i;
        if (row >= M) continue;
        #pragma unroll
        for (int j = 0; j < 8; j += 4) {
            int col = bn + tx + j;
            float4 bb = *(const float4*)&bias[col];
            float4 c;
            c.x = acc[i][j + 0] + bb.x;
            c.y = acc[i][j + 1] + bb.y;
            c.z = acc[i][j + 2] + bb.z;
            c.w = acc[i][j + 3] + bb.w;
            if (res) {
                float4 rr = *(const float4*)&res[(size_t)row * N + col];
                c.x += rr.x; c.y += rr.y; c.z += rr.z; c.w += rr.w;
            }
            *(float4*)&C[(size_t)row * N + col] = c;
        }
    }
}

// ---------------------------------------------------------------------------
// Block-sparse Emformer attention + residual (+h).
// Chunk i (grid.x): queries = [32 right rows @32i if i<7] + [128 body rows].
// Keys = [32 right @32i if i<7] + body [128*max(i-1,0), 128*(i+1)).
// One thread = one query (online softmax, o[64] in regs).
// K/V tiles staged in dynamic smem: 288*64*2 floats = 147456 B.
// ---------------------------------------------------------------------------
__global__ void attn_kernel(const float* __restrict__ Q,
                            const float* __restrict__ K,
                            const float* __restrict__ V,
                            const float* __restrict__ Hh,
                            float* __restrict__ O)
{
    int ci = blockIdx.x;   // chunk 0..7
    int hh = blockIdx.y;   // head
    int b  = blockIdx.z;   // batch

    extern __shared__ float sm[];
    float* Ks = sm;                // [nk][64]
    float* Vs = sm + 288 * 64;

    int nkr   = (ci < 7) ? 32 : 0;
    int body0 = (ci >= 1) ? 128 * (ci - 1) : 0;
    int body1 = 128 * (ci + 1);
    int nk    = nkr + (body1 - body0);
    int nq    = (ci < 7) ? 160 : 128;
    int base  = b * TTOT;
    int tid   = threadIdx.x;

    // cooperative K/V staging (float4 granularity)
    for (int idx = tid; idx < nk * 16; idx += blockDim.x) {
        int j  = idx >> 4;
        int d4 = idx & 15;
        int krow = (j < nkr) ? (32 * ci + j) : (NRIGHT + body0 + (j - nkr));
        size_t off = (size_t)(base + krow) * DMODEL + hh * DK;
        ((float4*)Ks)[idx] = ((const float4*)(K + off))[d4];
        ((float4*)Vs)[idx] = ((const float4*)(V + off))[d4];
    }
    __syncthreads();

    if (tid >= nq) return;

    int qrow;
    if (ci < 7) qrow = (tid < 32) ? (32 * ci + tid) : (NRIGHT + 128 * ci + tid - 32);
    else        qrow = NRIGHT + 128 * 7 + tid;

    size_t qoff = (size_t)(base + qrow) * DMODEL + hh * DK;
    float qv[64];
    {
        const float4* qp = (const float4*)(Q + qoff);
        #pragma unroll
        for (int d4 = 0; d4 < 16; d4++) {
            float4 t = qp[d4];
            qv[4*d4+0] = t.x * 0.125f;   // 1/sqrt(64)
            qv[4*d4+1] = t.y * 0.125f;
            qv[4*d4+2] = t.z * 0.125f;
            qv[4*d4+3] = t.w * 0.125f;
        }
    }

    float m = -1e30f, l = 0.f;
    float o[64];
    #pragma unroll
    for (int d = 0; d < 64; d++) o[d] = 0.f;

    for (int j = 0; j < nk; j++) {
        const float4* kr = (const float4*)(Ks + j * 64);
        float s = 0.f;
        #pragma unroll
        for (int d4 = 0; d4 < 16; d4++) {
            float4 t = kr[d4];
            s += qv[4*d4+0]*t.x + qv[4*d4+1]*t.y + qv[4*d4+2]*t.z + qv[4*d4+3]*t.w;
        }
        if (s > m) {                       // rare rescale
            float c = __expf(m - s);
            l *= c;
            #pragma unroll
            for (int d = 0; d < 64; d++) o[d] *= c;
            m = s;
        }
        float p = __expf(s - m);
        l += p;
        const float4* vr = (const float4*)(Vs + j * 64);
        #pragma unroll
        for (int d4 = 0; d4 < 16; d4++) {
            float4 t = vr[d4];
            o[4*d4+0] += p * t.x;
            o[4*d4+1] += p * t.y;
            o[4*d4+2] += p * t.z;
            o[4*d4+3] += p * t.w;
        }
    }

    float inv = 1.0f / l;
    const float4* hp = (const float4*)(Hh + qoff);
    float4* op = (float4*)(O + qoff);
    #pragma unroll
    for (int d4 = 0; d4 < 16; d4++) {
        float4 hv = hp[d4];
        float4 c;
        c.x = o[4*d4+0] * inv + hv.x;
        c.y = o[4*d4+1] * inv + hv.y;
        c.z = o[4*d4+2] * inv + hv.z;
        c.w = o[4*d4+3] * inv + hv.w;
        op[d4] = c;
    }
}

// ---------------------------------------------------------------------------
extern "C" void kernel_launch(void* const* d_in, const int* in_sizes, int n_in,
                              void* d_out, int out_size)
{
    const float* input       = (const float*)d_in[0];
    const float* ln_in_scale = (const float*)d_in[1];
    const float* ln_in_bias  = (const float*)d_in[2];
    const float* Wq          = (const float*)d_in[3];
    const float* bq          = (const float*)d_in[4];
    const float* Wk          = (const float*)d_in[5];
    const float* bk          = (const float*)d_in[6];
    const float* Wv          = (const float*)d_in[7];
    const float* bv          = (const float*)d_in[8];
    const float* ln1_scale   = (const float*)d_in[9];
    const float* ln1_bias    = (const float*)d_in[10];
    const float* W1          = (const float*)d_in[11];
    const float* b1          = (const float*)d_in[12];
    const float* W2          = (const float*)d_in[13];
    const float* b2          = (const float*)d_in[14];
    const float* ln2_scale   = (const float*)d_in[15];
    const float* ln2_bias    = (const float*)d_in[16];
    // d_in[17] = mask: unused (mask is analytic)

    float *h, *q, *k, *v, *attn, *y1, *y2, *xb;
    cudaGetSymbolAddress((void**)&h,    g_h);
    cudaGetSymbolAddress((void**)&q,    g_q);
    cudaGetSymbolAddress((void**)&k,    g_k);
    cudaGetSymbolAddress((void**)&v,    g_v);
    cudaGetSymbolAddress((void**)&attn, g_attn);
    cudaGetSymbolAddress((void**)&y1,   g_y1);
    cudaGetSymbolAddress((void**)&y2,   g_y2);
    cudaGetSymbolAddress((void**)&xb,   g_x);

    cudaFuncSetAttribute(attn_kernel,
                         cudaFuncAttributeMaxDynamicSharedMemorySize, 147456);

    const int M = MROWS;
    dim3 gemmDD(DMODEL / 128, (M + 127) / 128);   // (8, 20)
    dim3 gemmDF(FDIM / 128,   (M + 127) / 128);   // (32, 20)
    dim3 attnGrid(NCHUNK, NHEAD, BATCH);          // (8, 16, 2)

    const float* x = input;
    for (int l = 0; l < 2; l++) {
        size_t oD  = (size_t)l * DMODEL;
        size_t oDD = (size_t)l * DMODEL * DMODEL;
        size_t oDF = (size_t)l * DMODEL * FDIM;
        size_t oF  = (size_t)l * FDIM;

        ln_kernel<<<M, 256>>>(x, ln_in_scale + oD, ln_in_bias + oD, h);

        sgemm_kernel<<<gemmDD, 256>>>(h, Wq + oDD, bq + oD, nullptr, q, M, DMODEL, DMODEL);
        sgemm_kernel<<<gemmDD, 256>>>(h, Wk + oDD, bk + oD, nullptr, k, M, DMODEL, DMODEL);
        sgemm_kernel<<<gemmDD, 256>>>(h, Wv + oDD, bv + oD, nullptr, v, M, DMODEL, DMODEL);

        attn_kernel<<<attnGrid, 192, 147456>>>(q, k, v, h, attn);

        ln_kernel<<<M, 256>>>(attn, ln1_scale + oD, ln1_bias + oD, h);

        sgemm_kernel<<<gemmDF, 256>>>(h, W1 + oDF, b1 + oF, nullptr, y1, M, FDIM, DMODEL);
        sgemm_kernel<<<gemmDD, 256>>>(y1, W2 + oDF, b2 + oD, attn, y2, M, DMODEL, FDIM);

        float* dst = (l == 0) ? xb : (float*)d_out;
        ln_kernel<<<M, 256>>>(y2, ln2_scale + oD, ln2_bias + oD, dst);
        x = xb;
    }
}

// round 2
// speedup vs baseline: 2.3607x; 2.3607x over previous
#include <cuda_runtime.h>
#include <cuda_bf16.h>
#include <math.h>

// ---------------------------------------------------------------------------
// EmformerEncoder  B=2, T=1248 (224 right-ctx + 1024 body), D=1024, H=16,
// DK=64, F=4096, L=2.  Analytic block-sparse mask (CHUNK=128,LEFT=128,RIGHT=32).
// Round 1: GEMMs on tensor cores via bf16x3 split (mma.sync.m16n8k16),
//          fp32-accurate (rel_err ~1e-5). Attention/LN stay fp32 SIMT.
// ---------------------------------------------------------------------------

#define TTOT   1248
#define NRIGHT 224
#define BATCH  2
#define MROWS  (BATCH * TTOT)   // 2496
#define DMODEL 1024
#define NHEAD  16
#define DK     64
#define FDIM   4096
#define NCHUNK 8

// ---- scratch (device globals; no allocation allowed) ----------------------
__device__ float g_h[MROWS * DMODEL];
__device__ float g_q[MROWS * DMODEL];
__device__ float g_k[MROWS * DMODEL];
__device__ float g_v[MROWS * DMODEL];
__device__ float g_attn[MROWS * DMODEL];
__device__ float g_y1[MROWS * FDIM];
__device__ float g_y2[MROWS * DMODEL];
__device__ float g_x[MROWS * DMODEL];

// ---------------------------------------------------------------------------
// LayerNorm: one block per row, 256 threads, float4 per thread
// ---------------------------------------------------------------------------
__global__ void ln_kernel(const float* __restrict__ X,
                          const float* __restrict__ sc,
                          const float* __restrict__ bi,
                          float* __restrict__ Y)
{
    int row = blockIdx.x;
    int t   = threadIdx.x;
    const float4* xr = (const float4*)(X + (size_t)row * DMODEL);
    float4 v = xr[t];
    float s  = v.x + v.y + v.z + v.w;
    float ss = v.x*v.x + v.y*v.y + v.z*v.z + v.w*v.w;
    #pragma unroll
    for (int off = 16; off; off >>= 1) {
        s  += __shfl_xor_sync(0xffffffffu, s,  off);
        ss += __shfl_xor_sync(0xffffffffu, ss, off);
    }
    __shared__ float redS[8], redQ[8];
    int w = t >> 5;
    if ((t & 31) == 0) { redS[w] = s; redQ[w] = ss; }
    __syncthreads();
    float S = 0.f, Q = 0.f;
    #pragma unroll
    for (int i = 0; i < 8; i++) { S += redS[i]; Q += redQ[i]; }
    float mean = S * (1.0f / DMODEL);
    float var  = Q * (1.0f / DMODEL) - mean * mean;
    float r    = rsqrtf(var + 1e-5f);
    float4 scv = ((const float4*)sc)[t];
    float4 bv  = ((const float4*)bi)[t];
    float4 o;
    o.x = (v.x - mean) * r * scv.x + bv.x;
    o.y = (v.y - mean) * r * scv.y + bv.y;
    o.z = (v.z - mean) * r * scv.z + bv.z;
    o.w = (v.w - mean) * r * scv.w + bv.w;
    ((float4*)(Y + (size_t)row * DMODEL))[t] = o;
}

// ---------------------------------------------------------------------------
// bf16x3 tensor-core GEMM: C = A @ B + bias (+ res).
// 128x128 CTA tile, BK=16, 8 warps (2x4), warp tile 64x32,
// mma.sync.aligned.m16n8k16.row.col.f32.bf16.bf16.f32.
// Split: x = hi + lo (bf16 each); D += Ahi*Bhi + Ahi*Blo + Alo*Bhi.
// Smem padded: A rows stride 20 words, B rows stride 136 words -> all four
// fragment-load patterns are bank-conflict-free.
// ---------------------------------------------------------------------------
__device__ __forceinline__ void mma_bf16(float* c, const unsigned* a,
                                         unsigned b0, unsigned b1)
{
    asm volatile(
        "mma.sync.aligned.m16n8k16.row.col.f32.bf16.bf16.f32 "
        "{%0,%1,%2,%3}, {%4,%5,%6,%7}, {%8,%9}, {%0,%1,%2,%3};"
        : "+f"(c[0]), "+f"(c[1]), "+f"(c[2]), "+f"(c[3])
        : "r"(a[0]), "r"(a[1]), "r"(a[2]), "r"(a[3]), "r"(b0), "r"(b1));
}

__device__ __forceinline__ void split_bf16(float x, __nv_bfloat16& h, __nv_bfloat16& l)
{
    h = __float2bfloat16_rn(x);
    l = __float2bfloat16_rn(x - __bfloat162float(h));
}

__device__ __forceinline__ unsigned packb(__nv_bfloat16 lo, __nv_bfloat16 hi)
{
    __nv_bfloat162 p;
    p.x = lo;   // low 16 bits = lower-k element
    p.y = hi;
    return *(unsigned*)&p;
}

__global__ void gemm_bf16x3_kernel(const float* __restrict__ A,
                                   const float* __restrict__ B,
                                   const float* __restrict__ bias,
                                   const float* __restrict__ res,
                                   float* __restrict__ C,
                                   int M, int N, int K)
{
    // A tile: 128 rows x 16 k  (8 packed words/row, stride 20 words)
    // B tile: 16 k x 128 n     (8 k-pair rows,     stride 136 words)
    __shared__ unsigned Ah[128 * 20], Al[128 * 20];
    __shared__ unsigned Bh[8 * 136],  Bl[8 * 136];

    const int bm = blockIdx.y * 128;
    const int bn = blockIdx.x * 128;
    const int tid  = threadIdx.x;
    const int lane = tid & 31;
    const int wid  = tid >> 5;
    const int wm = (wid >> 2) * 64;     // 0 or 64
    const int wn = (wid & 3) * 32;      // 0,32,64,96
    const int g  = lane >> 2;           // group id 0..7
    const int qd = lane & 3;            // quad id 0..3

    float acc[4][4][4];
    #pragma unroll
    for (int i = 0; i < 4; i++)
        #pragma unroll
        for (int j = 0; j < 4; j++)
            #pragma unroll
            for (int r = 0; r < 4; r++) acc[i][j][r] = 0.f;

    for (int k0 = 0; k0 < K; k0 += 16) {
        // ---- fill A (hi/lo), 2 float4s per thread --------------------------
        #pragma unroll
        for (int it = 0; it < 2; it++) {
            int i  = tid + it * 256;          // 0..511
            int r  = i >> 2;                  // row 0..127
            int kc = (i & 3) * 4;             // 0,4,8,12
            float4 v = make_float4(0.f, 0.f, 0.f, 0.f);
            if (bm + r < M)
                v = *(const float4*)&A[(size_t)(bm + r) * K + k0 + kc];
            __nv_bfloat16 hx, lx, hy, ly, hz, lz, hw, lw;
            split_bf16(v.x, hx, lx); split_bf16(v.y, hy, ly);
            split_bf16(v.z, hz, lz); split_bf16(v.w, hw, lw);
            uint2 wh, wl;
            wh.x = packb(hx, hy); wh.y = packb(hz, hw);
            wl.x = packb(lx, ly); wl.y = packb(lz, lw);
            int wi = r * 20 + (kc >> 1);      // word index (even)
            *(uint2*)&Ah[wi] = wh;
            *(uint2*)&Al[wi] = wl;
        }
        // ---- fill B (hi/lo), k-pairs packed per word, 1 pass ---------------
        {
            int kp = tid >> 5;                // 0..7  (k pair)
            int n4 = (lane) * 4;              // 0..124
            const float4 e = *(const float4*)&B[(size_t)(k0 + 2 * kp) * N + bn + n4];
            const float4 o = *(const float4*)&B[(size_t)(k0 + 2 * kp + 1) * N + bn + n4];
            __nv_bfloat16 he[4], le[4], ho[4], lo_[4];
            split_bf16(e.x, he[0], le[0]); split_bf16(e.y, he[1], le[1]);
            split_bf16(e.z, he[2], le[2]); split_bf16(e.w, he[3], le[3]);
            split_bf16(o.x, ho[0], lo_[0]); split_bf16(o.y, ho[1], lo_[1]);
            split_bf16(o.z, ho[2], lo_[2]); split_bf16(o.w, ho[3], lo_[3]);
            uint4 wh, wl;
            wh.x = packb(he[0], ho[0]); wh.y = packb(he[1], ho[1]);
            wh.z = packb(he[2], ho[2]); wh.w = packb(he[3], ho[3]);
            wl.x = packb(le[0], lo_[0]); wl.y = packb(le[1], lo_[1]);
            wl.z = packb(le[2], lo_[2]); wl.w = packb(le[3], lo_[3]);
            int wi = kp * 136 + n4;
            *(uint4*)&Bh[wi] = wh;
            *(uint4*)&Bl[wi] = wl;
        }
        __syncthreads();

        // ---- fragments + MMAs ---------------------------------------------
        unsigned ah[4][4], al[4][4];
        #pragma unroll
        for (int mi = 0; mi < 4; mi++) {
            int ra = (wm + mi * 16 + g) * 20;
            int rb = (wm + mi * 16 + 8 + g) * 20;
            ah[mi][0] = Ah[ra + qd];     ah[mi][1] = Ah[rb + qd];
            ah[mi][2] = Ah[ra + 4 + qd]; ah[mi][3] = Ah[rb + 4 + qd];
            al[mi][0] = Al[ra + qd];     al[mi][1] = Al[rb + qd];
            al[mi][2] = Al[ra + 4 + qd]; al[mi][3] = Al[rb + 4 + qd];
        }
        #pragma unroll
        for (int ni = 0; ni < 4; ni++) {
            int n0 = wn + ni * 8 + g;
            unsigned bh0 = Bh[qd * 136 + n0];
            unsigned bh1 = Bh[(4 + qd) * 136 + n0];
            unsigned bl0 = Bl[qd * 136 + n0];
            unsigned bl1 = Bl[(4 + qd) * 136 + n0];
            #pragma unroll
            for (int mi = 0; mi < 4; mi++) {
                mma_bf16(acc[mi][ni], ah[mi], bh0, bh1);
                mma_bf16(acc[mi][ni], ah[mi], bl0, bl1);
                mma_bf16(acc[mi][ni], al[mi], bh0, bh1);
            }
        }
        __syncthreads();
    }

    // ---- epilogue: bias (+res), float2 stores ------------------------------
    #pragma unroll
    for (int mi = 0; mi < 4; mi++) {
        #pragma unroll
        for (int ni = 0; ni < 4; ni++) {
            int r0 = bm + wm + mi * 16 + g;
            int cc = bn + wn + ni * 8 + qd * 2;
            float2 bb = *(const float2*)&bias[cc];
            if (r0 < M) {
                float2 o;
                o.x = acc[mi][ni][0] + bb.x;
                o.y = acc[mi][ni][1] + bb.y;
                if (res) {
                    float2 rr = *(const float2*)&res[(size_t)r0 * N + cc];
                    o.x += rr.x; o.y += rr.y;
                }
                *(float2*)&C[(size_t)r0 * N + cc] = o;
            }
            int r1 = r0 + 8;
            if (r1 < M) {
                float2 o;
                o.x = acc[mi][ni][2] + bb.x;
                o.y = acc[mi][ni][3] + bb.y;
                if (res) {
                    float2 rr = *(const float2*)&res[(size_t)r1 * N + cc];
                    o.x += rr.x; o.y += rr.y;
                }
                *(float2*)&C[(size_t)r1 * N + cc] = o;
            }
        }
    }
}

// ---------------------------------------------------------------------------
// Block-sparse Emformer attention + residual (+h).  (unchanged from R0)
// ---------------------------------------------------------------------------
__global__ void attn_kernel(const float* __restrict__ Q,
                            const float* __restrict__ K,
                            const float* __restrict__ V,
                            const float* __restrict__ Hh,
                            float* __restrict__ O)
{
    int ci = blockIdx.x;
    int hh = blockIdx.y;
    int b  = blockIdx.z;

    extern __shared__ float sm[];
    float* Ks = sm;
    float* Vs = sm + 288 * 64;

    int nkr   = (ci < 7) ? 32 : 0;
    int body0 = (ci >= 1) ? 128 * (ci - 1) : 0;
    int body1 = 128 * (ci + 1);
    int nk    = nkr + (body1 - body0);
    int nq    = (ci < 7) ? 160 : 128;
    int base  = b * TTOT;
    int tid   = threadIdx.x;

    for (int idx = tid; idx < nk * 16; idx += blockDim.x) {
        int j  = idx >> 4;
        int d4 = idx & 15;
        int krow = (j < nkr) ? (32 * ci + j) : (NRIGHT + body0 + (j - nkr));
        size_t off = (size_t)(base + krow) * DMODEL + hh * DK;
        ((float4*)Ks)[idx] = ((const float4*)(K + off))[d4];
        ((float4*)Vs)[idx] = ((const float4*)(V + off))[d4];
    }
    __syncthreads();

    if (tid >= nq) return;

    int qrow;
    if (ci < 7) qrow = (tid < 32) ? (32 * ci + tid) : (NRIGHT + 128 * ci + tid - 32);
    else        qrow = NRIGHT + 128 * 7 + tid;

    size_t qoff = (size_t)(base + qrow) * DMODEL + hh * DK;
    float qv[64];
    {
        const float4* qp = (const float4*)(Q + qoff);
        #pragma unroll
        for (int d4 = 0; d4 < 16; d4++) {
            float4 t = qp[d4];
            qv[4*d4+0] = t.x * 0.125f;
            qv[4*d4+1] = t.y * 0.125f;
            qv[4*d4+2] = t.z * 0.125f;
            qv[4*d4+3] = t.w * 0.125f;
        }
    }

    float m = -1e30f, l = 0.f;
    float o[64];
    #pragma unroll
    for (int d = 0; d < 64; d++) o[d] = 0.f;

    for (int j = 0; j < nk; j++) {
        const float4* kr = (const float4*)(Ks + j * 64);
        float s = 0.f;
        #pragma unroll
        for (int d4 = 0; d4 < 16; d4++) {
            float4 t = kr[d4];
            s += qv[4*d4+0]*t.x + qv[4*d4+1]*t.y + qv[4*d4+2]*t.z + qv[4*d4+3]*t.w;
        }
        if (s > m) {
            float c = __expf(m - s);
            l *= c;
            #pragma unroll
            for (int d = 0; d < 64; d++) o[d] *= c;
            m = s;
        }
        float p = __expf(s - m);
        l += p;
        const float4* vr = (const float4*)(Vs + j * 64);
        #pragma unroll
        for (int d4 = 0; d4 < 16; d4++) {
            float4 t = vr[d4];
            o[4*d4+0] += p * t.x;
            o[4*d4+1] += p * t.y;
            o[4*d4+2] += p * t.z;
            o[4*d4+3] += p * t.w;
        }
    }

    float inv = 1.0f / l;
    const float4* hp = (const float4*)(Hh + qoff);
    float4* op = (float4*)(O + qoff);
    #pragma unroll
    for (int d4 = 0; d4 < 16; d4++) {
        float4 hv = hp[d4];
        float4 c;
        c.x = o[4*d4+0] * inv + hv.x;
        c.y = o[4*d4+1] * inv + hv.y;
        c.z = o[4*d4+2] * inv + hv.z;
        c.w = o[4*d4+3] * inv + hv.w;
        op[d4] = c;
    }
}

// ---------------------------------------------------------------------------
extern "C" void kernel_launch(void* const* d_in, const int* in_sizes, int n_in,
                              void* d_out, int out_size)
{
    const float* input       = (const float*)d_in[0];
    const float* ln_in_scale = (const float*)d_in[1];
    const float* ln_in_bias  = (const float*)d_in[2];
    const float* Wq          = (const float*)d_in[3];
    const float* bq          = (const float*)d_in[4];
    const float* Wk          = (const float*)d_in[5];
    const float* bk          = (const float*)d_in[6];
    const float* Wv          = (const float*)d_in[7];
    const float* bv          = (const float*)d_in[8];
    const float* ln1_scale   = (const float*)d_in[9];
    const float* ln1_bias    = (const float*)d_in[10];
    const float* W1          = (const float*)d_in[11];
    const float* b1          = (const float*)d_in[12];
    const float* W2          = (const float*)d_in[13];
    const float* b2          = (const float*)d_in[14];
    const float* ln2_scale   = (const float*)d_in[15];
    const float* ln2_bias    = (const float*)d_in[16];
    // d_in[17] = mask: unused (mask is analytic)

    float *h, *q, *k, *v, *attn, *y1, *y2, *xb;
    cudaGetSymbolAddress((void**)&h,    g_h);
    cudaGetSymbolAddress((void**)&q,    g_q);
    cudaGetSymbolAddress((void**)&k,    g_k);
    cudaGetSymbolAddress((void**)&v,    g_v);
    cudaGetSymbolAddress((void**)&attn, g_attn);
    cudaGetSymbolAddress((void**)&y1,   g_y1);
    cudaGetSymbolAddress((void**)&y2,   g_y2);
    cudaGetSymbolAddress((void**)&xb,   g_x);

    cudaFuncSetAttribute(attn_kernel,
                         cudaFuncAttributeMaxDynamicSharedMemorySize, 147456);

    const int M = MROWS;
    dim3 gemmDD(DMODEL / 128, (M + 127) / 128);   // (8, 20)
    dim3 gemmDF(FDIM / 128,   (M + 127) / 128);   // (32, 20)
    dim3 attnGrid(NCHUNK, NHEAD, BATCH);

    const float* x = input;
    for (int l = 0; l < 2; l++) {
        size_t oD  = (size_t)l * DMODEL;
        size_t oDD = (size_t)l * DMODEL * DMODEL;
        size_t oDF = (size_t)l * DMODEL * FDIM;
        size_t oF  = (size_t)l * FDIM;

        ln_kernel<<<M, 256>>>(x, ln_in_scale + oD, ln_in_bias + oD, h);

        gemm_bf16x3_kernel<<<gemmDD, 256>>>(h, Wq + oDD, bq + oD, nullptr, q, M, DMODEL, DMODEL);
        gemm_bf16x3_kernel<<<gemmDD, 256>>>(h, Wk + oDD, bk + oD, nullptr, k, M, DMODEL, DMODEL);
        gemm_bf16x3_kernel<<<gemmDD, 256>>>(h, Wv + oDD, bv + oD, nullptr, v, M, DMODEL, DMODEL);

        attn_kernel<<<attnGrid, 192, 147456>>>(q, k, v, h, attn);

        ln_kernel<<<M, 256>>>(attn, ln1_scale + oD, ln1_bias + oD, h);

        gemm_bf16x3_kernel<<<gemmDF, 256>>>(h, W1 + oDF, b1 + oF, nullptr, y1, M, FDIM, DMODEL);
        gemm_bf16x3_kernel<<<gemmDD, 256>>>(y1, W2 + oDF, b2 + oD, attn, y2, M, DMODEL, FDIM);

        float* dst = (l == 0) ? xb : (float*)d_out;
        ln_kernel<<<M, 256>>>(y2, ln2_scale + oD, ln2_bias + oD, dst);
        x = xb;
    }
}